// round 8
// baseline (speedup 1.0000x reference)
#include <cuda_runtime.h>
#include <cuda_fp16.h>
#include <math.h>
#include <stdint.h>

#define NB 2
#define LQ 2048
#define SK 2048
#define HH 8
#define DD 64
#define NHT (NB*HH)
#define NHLD (NB*HH*LQ*DD)   // 2,097,152
#define NROWS (NHT*LQ)       // 32768
#define ZSPLIT 4
#define TILES_PER_CTA 4
#define NGROUPS (16*NHT)     // (ltile, nh) groups = 256

// Scratch (layout [n][h][row][d]), fp16
__device__ __align__(256) __half g_Qh[NHLD];
__device__ __align__(256) __half g_Kh[NHLD];
__device__ __align__(256) float g_kpart[1024*DD];   // per-prep-block partial K sums
__device__ __align__(256) float g_ksum[NHT*DD];
__device__ __align__(256) unsigned int g_rowmax[NROWS];
__device__ __align__(256) int g_cnt[NGROUPS];

// ---------------------------------------------------------------------------
// PTX helpers
// ---------------------------------------------------------------------------
__device__ __forceinline__ uint32_t smem_u32_of(const void* p) {
    uint32_t a;
    asm("{ .reg .u64 t; cvta.to.shared.u64 t, %1; cvt.u32.u64 %0, t; }" : "=r"(a) : "l"(p));
    return a;
}
#define LDM4(r, addr) \
    asm volatile("ldmatrix.sync.aligned.m8n8.x4.shared.b16 {%0,%1,%2,%3}, [%4];" \
        : "=r"((r)[0]), "=r"((r)[1]), "=r"((r)[2]), "=r"((r)[3]) : "r"(addr))
#define MMAF16(c, a0, a1, a2, a3, b0, b1) \
    asm volatile("mma.sync.aligned.m16n8k16.row.col.f32.f16.f16.f32 " \
        "{%0,%1,%2,%3}, {%4,%5,%6,%7}, {%8,%9}, {%0,%1,%2,%3};" \
        : "+f"((c)[0]), "+f"((c)[1]), "+f"((c)[2]), "+f"((c)[3]) \
        : "r"(a0), "r"(a1), "r"(a2), "r"(a3), "r"(b0), "r"(b1))
#define CPA16(s, g) \
    asm volatile("cp.async.cg.shared.global [%0], [%1], 16;" :: "r"(s), "l"(g))
#define CPC()  asm volatile("cp.async.commit_group;" ::: "memory")
#define CPW1() asm volatile("cp.async.wait_group 1;" ::: "memory")
#define CPW0() asm volatile("cp.async.wait_group 0;" ::: "memory")

// SMEM byte offsets
#define A_OFF 0
#define B_OFF 16384             // + (t%3)*16384, 3 stages
#define SMEM_TOTAL 65536

// ---------------------------------------------------------------------------
// Kernel A: feature map + mask + [n,l,h,d]->[n,h,l,d], fp16 out.
// Each block covers 32 rows of one (n,h); also reduces its K rows into
// g_kpart[block][64]. Zeroes g_rowmax and g_cnt.
// ---------------------------------------------------------------------------
__global__ __launch_bounds__(256) void prep_kernel(
    const float* __restrict__ q, const float* __restrict__ k,
    const float* __restrict__ qm, const float* __restrict__ km)
{
    const int tid = threadIdx.x;
    int idx = blockIdx.x * 256 + tid;              // 8-element chunk index
    if (idx < NROWS) g_rowmax[idx] = 0u;
    if (idx < NGROUPS) g_cnt[idx] = 0;

    int e = idx << 3;                              // first element
    int d = e & 63;
    int l = (e >> 6) & 2047;
    int h = (e >> 17) & 7;
    int n = e >> 20;
    size_t src = ((((size_t)n * 2048 + l) * 8 + h) << 6) + d;

    float4 q0 = *(const float4*)(q + src);
    float4 q1 = *(const float4*)(q + src + 4);
    float4 k0 = *(const float4*)(k + src);
    float4 k1 = *(const float4*)(k + src + 4);
    float qmv = qm[n * 2048 + l];
    float kmv = km[n * 2048 + l];

    float fq[8] = {q0.x, q0.y, q0.z, q0.w, q1.x, q1.y, q1.z, q1.w};
    float fk[8] = {k0.x, k0.y, k0.z, k0.w, k1.x, k1.y, k1.z, k1.w};

    float pk[8];
    uint4 oq, ok;
    uint32_t* pqo = (uint32_t*)&oq;
    uint32_t* pko = (uint32_t*)&ok;
    #pragma unroll
    for (int j = 0; j < 4; j++) {
        float ax = ((fq[2*j]   > 0.f) ? (fq[2*j]   + 1.f) : __expf(fq[2*j]))   * qmv;
        float ay = ((fq[2*j+1] > 0.f) ? (fq[2*j+1] + 1.f) : __expf(fq[2*j+1])) * qmv;
        float bx = ((fk[2*j]   > 0.f) ? (fk[2*j]   + 1.f) : __expf(fk[2*j]))   * kmv;
        float by = ((fk[2*j+1] > 0.f) ? (fk[2*j+1] + 1.f) : __expf(fk[2*j+1])) * kmv;
        pk[2*j] = bx; pk[2*j+1] = by;
        __half2 hq = __floats2half2_rn(ax, ay);
        __half2 hk = __floats2half2_rn(bx, by);
        pqo[j] = *(uint32_t*)&hq;
        pko[j] = *(uint32_t*)&hk;
    }
    ((uint4*)g_Qh)[idx] = oq;
    ((uint4*)g_Kh)[idx] = ok;

    // --- block-local K partial sum: 32 rows x 64 d -> 64 floats ---
    __shared__ float stage[32][72];
    const int row = tid >> 3;
    const int dc  = (tid & 7) * 8;
    #pragma unroll
    for (int j = 0; j < 8; j++) stage[row][dc + j] = pk[j];
    __syncthreads();
    if (tid < 64) {
        float s = 0.f;
        #pragma unroll
        for (int r = 0; r < 32; r++) s += stage[r][tid];
        g_kpart[blockIdx.x * 64 + tid] = s;
    }
}

// ---------------------------------------------------------------------------
// Kernel B: reduce per-block partials. grid=NHT, block=64; blocks per nh = 64.
// ---------------------------------------------------------------------------
__global__ __launch_bounds__(64) void ksum_final_kernel()
{
    int nh = blockIdx.x;
    int d = threadIdx.x;
    float s = 0.f;
    #pragma unroll 8
    for (int b = 0; b < 64; b++) s += g_kpart[(nh * 64 + b) * 64 + d];
    g_ksum[nh * 64 + d] = s;
}

// ---------------------------------------------------------------------------
// Kernel C: fp16 HMMA score GEMM + row-max + fused last-CTA finalize.
// grid=(16 ltile, 16 nh, ZSPLIT), block=256 (8 warps 4x2), 2 CTAs/SM.
// ---------------------------------------------------------------------------
__global__ void __launch_bounds__(256, 2) attn_mma_kernel(
    const float* __restrict__ queries,
    const float* __restrict__ qmask,
    const float* __restrict__ W,
    const float* __restrict__ bias,
    float* __restrict__ out)
{
    extern __shared__ char sm[];
    const uint32_t smu = smem_u32_of(sm);

    const int tid  = threadIdx.x;
    const int lane = tid & 31;
    const int wid  = tid >> 5;
    const int wx   = wid & 1;       // n-block (64 cols)
    const int wy   = wid >> 1;      // m-block (32 rows)
    const int nh   = blockIdx.y;
    const int l0   = blockIdx.x * 128;
    const int ts0  = blockIdx.z * TILES_PER_CTA;

    const int mat    = lane >> 3;
    const int rin    = lane & 7;
    const int a_row  = wy * 32 + (mat & 1) * 8 + rin;
    const int a_kc   = mat >> 1;
    const int b_roff = wx * 64 + (mat >> 1) * 8 + rin;
    const int b_kc   = mat & 1;

    const char* kh_base = (const char*)(g_Kh + (size_t)nh * SK * DD);

    auto issue_b = [&](int t) {
        uint32_t bu = smu + B_OFF + (t % 3) * 16384;
        const char* gk = kh_base + (size_t)(ts0 + t) * 128 * DD * 2;
        #pragma unroll
        for (int kk = 0; kk < 4; kk++) {
            int c = tid + kk * 256;
            int row = c >> 3, dc = c & 7;
            uint32_t sw = row * 128 + ((dc ^ (row & 7)) << 4);
            CPA16(bu + sw, gk + c * 16);
        }
    };

    issue_b(0); CPC();
    issue_b(1); CPC();

    // --- A tile (Q fp16, 128 x 64): LDG + swizzled STS ---
    {
        const char* qh = (const char*)(g_Qh + ((size_t)nh * LQ + l0) * DD);
        #pragma unroll
        for (int c = tid; c < 1024; c += 256) {
            int row = c >> 3, dc = c & 7;
            uint32_t dst = row * 128 + ((dc ^ (row & 7)) << 4);
            *(uint4*)(sm + A_OFF + dst) = *(const uint4*)(qh + c * 16);
        }
    }

    float mA[2] = {0.f, 0.f};
    float mB[2] = {0.f, 0.f};

    for (int t = 0; t < TILES_PER_CTA; t++) {
        if (t + 1 < TILES_PER_CTA) { CPW1(); }
        else                       { CPW0(); }
        __syncthreads();                        // stage t visible; t-1 compute done
        if (t + 2 < TILES_PER_CTA) { issue_b(t + 2); CPC(); }

        const uint32_t Bu = smu + B_OFF + (t % 3) * 16384;
        float acc[2][8][4];
        #pragma unroll
        for (int i = 0; i < 2; i++)
            #pragma unroll
            for (int j = 0; j < 8; j++)
                acc[i][j][0] = acc[i][j][1] = acc[i][j][2] = acc[i][j][3] = 0.f;

        #pragma unroll
        for (int ks = 0; ks < 4; ks++) {
            const int kb = ks * 2;
            uint32_t ah[2][4];
            #pragma unroll
            for (int i = 0; i < 2; i++) {
                int ar = a_row + 16 * i;
                uint32_t ad = smu + A_OFF + ar * 128 + (((a_kc + kb) ^ (ar & 7)) << 4);
                LDM4(ah[i], ad);
            }
            uint32_t rb[4][4];
            #pragma unroll
            for (int jp = 0; jp < 4; jp++) {
                int br = b_roff + jp * 16;
                uint32_t bd = Bu + br * 128 + (((b_kc + kb) ^ (br & 7)) << 4);
                LDM4(rb[jp], bd);
            }
            #pragma unroll
            for (int jp = 0; jp < 4; jp++)
                #pragma unroll
                for (int i = 0; i < 2; i++) {
                    MMAF16(acc[i][jp*2],   ah[i][0], ah[i][1], ah[i][2], ah[i][3], rb[jp][0], rb[jp][1]);
                    MMAF16(acc[i][jp*2+1], ah[i][0], ah[i][1], ah[i][2], ah[i][3], rb[jp][2], rb[jp][3]);
                }
        }

        #pragma unroll
        for (int i = 0; i < 2; i++)
            #pragma unroll
            for (int j = 0; j < 8; j++) {
                mA[i] = fmaxf(mA[i], fmaxf(acc[i][j][0], acc[i][j][1]));
                mB[i] = fmaxf(mB[i], fmaxf(acc[i][j][2], acc[i][j][3]));
            }
    }

    // --- reduce max across lane%4, atomicMax (uint order == float order, >=0) ---
    #pragma unroll
    for (int off = 1; off <= 2; off <<= 1) {
        #pragma unroll
        for (int i = 0; i < 2; i++) {
            mA[i] = fmaxf(mA[i], __shfl_xor_sync(0xffffffff, mA[i], off));
            mB[i] = fmaxf(mB[i], __shfl_xor_sync(0xffffffff, mB[i], off));
        }
    }
    if ((lane & 3) == 0) {
        int r = lane >> 2;
        unsigned int* rm = g_rowmax + nh * LQ + l0;
        #pragma unroll
        for (int i = 0; i < 2; i++) {
            atomicMax(rm + wy * 32 + i * 16 + r,     __float_as_uint(mA[i]));
            atomicMax(rm + wy * 32 + i * 16 + r + 8, __float_as_uint(mB[i]));
        }
    }
    __threadfence();

    // --- last CTA of this (ltile, nh) group runs the finalize ---
    __shared__ int is_last;
    __syncthreads();                          // all atomicMax issued before count
    if (tid == 0) {
        int v = atomicAdd(&g_cnt[blockIdx.x * NHT + nh], 1);
        is_last = (v == ZSPLIT - 1);
    }
    __syncthreads();
    if (!is_last) return;
    __threadfence();                          // acquire: see other CTAs' rowmax

    float* gate_s = (float*)sm;               // reuse A region (MMA done)
    float* ks_s   = (float*)(sm + 512);
    if (tid < 64) ks_s[tid] = g_ksum[nh * 64 + tid];
    __syncthreads();

    const int n = nh >> 3;
    const int h = nh & 7;
    if (tid < 128) {
        const int l = l0 + tid;
        float mean = 0.f;
        const uint4* ph = (const uint4*)(g_Qh + ((size_t)nh * LQ + l) * DD);
        #pragma unroll
        for (int c = 0; c < 4; c++) {
            uint4 v = ph[c];
            const uint32_t* w32 = (const uint32_t*)&v;
            #pragma unroll
            for (int w = 0; w < 4; w++) {
                float2 f = __half22float2(*(const __half2*)&w32[w]);
                mean += f.x * ks_s[c * 16 + w * 2];
                mean += f.y * ks_s[c * 16 + w * 2 + 1];
            }
        }
        mean *= (1.0f / (float)SK);
        float mx = __uint_as_float(g_rowmax[nh * LQ + l]);
        float lg = fmaf(mean, W[0], fmaf(mx, W[1], bias[0]));
        float gate = 1.0f / (1.0f + __expf(-lg));
        gate_s[tid] = gate * qmask[n * LQ + l];
    }
    __syncthreads();

    {
        const int lrow = tid >> 1;
        const int half = tid & 1;
        const int l = l0 + lrow;
        float s = gate_s[lrow];
        size_t obase = ((((size_t)n * LQ + l) * HH + h) << 6) + half * 32;
        const float4* qs = (const float4*)(queries + obase);
        float4* dst = (float4*)(out + obase);
        #pragma unroll
        for (int j = 0; j < 8; j++) {
            float4 v = qs[j];
            v.x *= s; v.y *= s; v.z *= s; v.w *= s;
            dst[j] = v;
        }
    }
}

// ---------------------------------------------------------------------------
extern "C" void kernel_launch(void* const* d_in, const int* in_sizes, int n_in,
                              void* d_out, int out_size)
{
    const float* queries = (const float*)d_in[0];
    const float* keys    = (const float*)d_in[1];
    const float* q_mask  = (const float*)d_in[3];
    const float* kv_mask = (const float*)d_in[4];
    const float* W       = (const float*)d_in[5];
    const float* b       = (const float*)d_in[6];
    float* out = (float*)d_out;

    prep_kernel<<<(NHLD / 8) / 256, 256>>>(queries, keys, q_mask, kv_mask);
    ksum_final_kernel<<<NHT, 64>>>();

    cudaFuncSetAttribute(attn_mma_kernel,
                         cudaFuncAttributeMaxDynamicSharedMemorySize, SMEM_TOTAL);
    dim3 grid(LQ / 128, NHT, ZSPLIT);
    attn_mma_kernel<<<grid, 256, SMEM_TOTAL>>>(queries, q_mask, W, b, out);
}

// round 9
// speedup vs baseline: 1.0491x; 1.0491x over previous
#include <cuda_runtime.h>
#include <cuda_fp16.h>
#include <math.h>
#include <stdint.h>

#define NB 2
#define LQ 2048
#define SK 2048
#define HH 8
#define DD 64
#define NHT (NB*HH)
#define NHLD (NB*HH*LQ*DD)   // 2,097,152
#define NROWS (NHT*LQ)       // 32768
#define ZSPLIT 4
#define TILES_PER_CTA 4

// Scratch (layout [n][h][row][d]), fp16
__device__ __align__(256) __half g_Qh[NHLD];
__device__ __align__(256) __half g_Kh[NHLD];
__device__ __align__(256) float g_kpart[1024*DD];   // per-prep-block partial K sums
__device__ __align__(256) float g_ksum[NHT*DD];
__device__ __align__(256) unsigned int g_rowmax[NROWS];

// ---------------------------------------------------------------------------
// PTX helpers
// ---------------------------------------------------------------------------
__device__ __forceinline__ uint32_t smem_u32_of(const void* p) {
    uint32_t a;
    asm("{ .reg .u64 t; cvta.to.shared.u64 t, %1; cvt.u32.u64 %0, t; }" : "=r"(a) : "l"(p));
    return a;
}
#define LDM4(r, addr) \
    asm volatile("ldmatrix.sync.aligned.m8n8.x4.shared.b16 {%0,%1,%2,%3}, [%4];" \
        : "=r"((r)[0]), "=r"((r)[1]), "=r"((r)[2]), "=r"((r)[3]) : "r"(addr))
#define MMAF16(c, a0, a1, a2, a3, b0, b1) \
    asm volatile("mma.sync.aligned.m16n8k16.row.col.f32.f16.f16.f32 " \
        "{%0,%1,%2,%3}, {%4,%5,%6,%7}, {%8,%9}, {%0,%1,%2,%3};" \
        : "+f"((c)[0]), "+f"((c)[1]), "+f"((c)[2]), "+f"((c)[3]) \
        : "r"(a0), "r"(a1), "r"(a2), "r"(a3), "r"(b0), "r"(b1))
#define CPA16(s, g) \
    asm volatile("cp.async.cg.shared.global [%0], [%1], 16;" :: "r"(s), "l"(g))
#define CPC()  asm volatile("cp.async.commit_group;" ::: "memory")
#define CPW1() asm volatile("cp.async.wait_group 1;" ::: "memory")
#define CPW0() asm volatile("cp.async.wait_group 0;" ::: "memory")

// SMEM byte offsets
#define A_OFF 0
#define B_OFF 16384             // + (t%3)*16384, 3 stages
#define SMEM_TOTAL 65536

// ---------------------------------------------------------------------------
// Kernel A: feature map + mask + [n,l,h,d]->[n,h,l,d], fp16 out.
// Each block covers 32 rows of one (n,h); reduces its K rows into
// g_kpart[block][64]. Zeroes g_rowmax.
// ---------------------------------------------------------------------------
__global__ __launch_bounds__(256) void prep_kernel(
    const float* __restrict__ q, const float* __restrict__ k,
    const float* __restrict__ qm, const float* __restrict__ km)
{
    const int tid = threadIdx.x;
    int idx = blockIdx.x * 256 + tid;              // 8-element chunk index
    if (idx < NROWS) g_rowmax[idx] = 0u;

    int e = idx << 3;                              // first element
    int d = e & 63;
    int l = (e >> 6) & 2047;
    int h = (e >> 17) & 7;
    int n = e >> 20;
    size_t src = ((((size_t)n * 2048 + l) * 8 + h) << 6) + d;

    float4 q0 = *(const float4*)(q + src);
    float4 q1 = *(const float4*)(q + src + 4);
    float4 k0 = *(const float4*)(k + src);
    float4 k1 = *(const float4*)(k + src + 4);
    float qmv = qm[n * 2048 + l];
    float kmv = km[n * 2048 + l];

    float fq[8] = {q0.x, q0.y, q0.z, q0.w, q1.x, q1.y, q1.z, q1.w};
    float fk[8] = {k0.x, k0.y, k0.z, k0.w, k1.x, k1.y, k1.z, k1.w};

    float pk[8];
    uint4 oq, ok;
    uint32_t* pqo = (uint32_t*)&oq;
    uint32_t* pko = (uint32_t*)&ok;
    #pragma unroll
    for (int j = 0; j < 4; j++) {
        float ax = ((fq[2*j]   > 0.f) ? (fq[2*j]   + 1.f) : __expf(fq[2*j]))   * qmv;
        float ay = ((fq[2*j+1] > 0.f) ? (fq[2*j+1] + 1.f) : __expf(fq[2*j+1])) * qmv;
        float bx = ((fk[2*j]   > 0.f) ? (fk[2*j]   + 1.f) : __expf(fk[2*j]))   * kmv;
        float by = ((fk[2*j+1] > 0.f) ? (fk[2*j+1] + 1.f) : __expf(fk[2*j+1])) * kmv;
        pk[2*j] = bx; pk[2*j+1] = by;
        __half2 hq = __floats2half2_rn(ax, ay);
        __half2 hk = __floats2half2_rn(bx, by);
        pqo[j] = *(uint32_t*)&hq;
        pko[j] = *(uint32_t*)&hk;
    }
    ((uint4*)g_Qh)[idx] = oq;
    ((uint4*)g_Kh)[idx] = ok;

    // --- block-local K partial sum: 32 rows x 64 d -> 64 floats ---
    __shared__ float stage[32][72];
    const int row = tid >> 3;
    const int dc  = (tid & 7) * 8;
    #pragma unroll
    for (int j = 0; j < 8; j++) stage[row][dc + j] = pk[j];
    __syncthreads();
    if (tid < 64) {
        float s = 0.f;
        #pragma unroll
        for (int r = 0; r < 32; r++) s += stage[r][tid];
        g_kpart[blockIdx.x * 64 + tid] = s;
    }
}

// ---------------------------------------------------------------------------
// Kernel B: reduce per-block partials. grid=NHT, block=64; 64 blocks per nh.
// ---------------------------------------------------------------------------
__global__ __launch_bounds__(64) void ksum_final_kernel()
{
    int nh = blockIdx.x;
    int d = threadIdx.x;
    float s = 0.f;
    #pragma unroll 8
    for (int b = 0; b < 64; b++) s += g_kpart[(nh * 64 + b) * 64 + d];
    g_ksum[nh * 64 + d] = s;
}

// ---------------------------------------------------------------------------
// Kernel C: fp16 HMMA score GEMM + row-max via atomicMax (lean, no epilogue).
// grid=(16 ltile, 16 nh, ZSPLIT), block=256 (8 warps 4x2), 2 CTAs/SM.
// 3-stage cp.async ring, one __syncthreads per tile.
// ---------------------------------------------------------------------------
__global__ void __launch_bounds__(256, 2) attn_mma_kernel()
{
    extern __shared__ char sm[];
    const uint32_t smu = smem_u32_of(sm);

    const int tid  = threadIdx.x;
    const int lane = tid & 31;
    const int wid  = tid >> 5;
    const int wx   = wid & 1;       // n-block (64 cols)
    const int wy   = wid >> 1;      // m-block (32 rows)
    const int nh   = blockIdx.y;
    const int l0   = blockIdx.x * 128;
    const int ts0  = blockIdx.z * TILES_PER_CTA;

    const int mat    = lane >> 3;
    const int rin    = lane & 7;
    const int a_row  = wy * 32 + (mat & 1) * 8 + rin;
    const int a_kc   = mat >> 1;
    const int b_roff = wx * 64 + (mat >> 1) * 8 + rin;
    const int b_kc   = mat & 1;

    const char* kh_base = (const char*)(g_Kh + (size_t)nh * SK * DD);

    auto issue_b = [&](int t) {
        uint32_t bu = smu + B_OFF + (t % 3) * 16384;
        const char* gk = kh_base + (size_t)(ts0 + t) * 128 * DD * 2;
        #pragma unroll
        for (int kk = 0; kk < 4; kk++) {
            int c = tid + kk * 256;
            int row = c >> 3, dc = c & 7;
            uint32_t sw = row * 128 + ((dc ^ (row & 7)) << 4);
            CPA16(bu + sw, gk + c * 16);
        }
    };

    issue_b(0); CPC();
    issue_b(1); CPC();

    // --- A tile (Q fp16, 128 x 64): LDG + swizzled STS (overlaps cp.async) ---
    {
        const char* qh = (const char*)(g_Qh + ((size_t)nh * LQ + l0) * DD);
        #pragma unroll
        for (int c = tid; c < 1024; c += 256) {
            int row = c >> 3, dc = c & 7;
            uint32_t dst = row * 128 + ((dc ^ (row & 7)) << 4);
            *(uint4*)(sm + A_OFF + dst) = *(const uint4*)(qh + c * 16);
        }
    }

    float mA[2] = {0.f, 0.f};
    float mB[2] = {0.f, 0.f};

    for (int t = 0; t < TILES_PER_CTA; t++) {
        if (t + 1 < TILES_PER_CTA) { CPW1(); }
        else                       { CPW0(); }
        __syncthreads();                        // stage t visible; t-1 compute done
        if (t + 2 < TILES_PER_CTA) { issue_b(t + 2); CPC(); }

        const uint32_t Bu = smu + B_OFF + (t % 3) * 16384;
        float acc[2][8][4];
        #pragma unroll
        for (int i = 0; i < 2; i++)
            #pragma unroll
            for (int j = 0; j < 8; j++)
                acc[i][j][0] = acc[i][j][1] = acc[i][j][2] = acc[i][j][3] = 0.f;

        #pragma unroll
        for (int ks = 0; ks < 4; ks++) {
            const int kb = ks * 2;
            uint32_t ah[2][4];
            #pragma unroll
            for (int i = 0; i < 2; i++) {
                int ar = a_row + 16 * i;
                uint32_t ad = smu + A_OFF + ar * 128 + (((a_kc + kb) ^ (ar & 7)) << 4);
                LDM4(ah[i], ad);
            }
            uint32_t rb[4][4];
            #pragma unroll
            for (int jp = 0; jp < 4; jp++) {
                int br = b_roff + jp * 16;
                uint32_t bd = Bu + br * 128 + (((b_kc + kb) ^ (br & 7)) << 4);
                LDM4(rb[jp], bd);
            }
            #pragma unroll
            for (int jp = 0; jp < 4; jp++)
                #pragma unroll
                for (int i = 0; i < 2; i++) {
                    MMAF16(acc[i][jp*2],   ah[i][0], ah[i][1], ah[i][2], ah[i][3], rb[jp][0], rb[jp][1]);
                    MMAF16(acc[i][jp*2+1], ah[i][0], ah[i][1], ah[i][2], ah[i][3], rb[jp][2], rb[jp][3]);
                }
        }

        #pragma unroll
        for (int i = 0; i < 2; i++)
            #pragma unroll
            for (int j = 0; j < 8; j++) {
                mA[i] = fmaxf(mA[i], fmaxf(acc[i][j][0], acc[i][j][1]));
                mB[i] = fmaxf(mB[i], fmaxf(acc[i][j][2], acc[i][j][3]));
            }
    }

    // --- reduce max across lane%4, atomicMax (uint order == float order, >=0) ---
    #pragma unroll
    for (int off = 1; off <= 2; off <<= 1) {
        #pragma unroll
        for (int i = 0; i < 2; i++) {
            mA[i] = fmaxf(mA[i], __shfl_xor_sync(0xffffffff, mA[i], off));
            mB[i] = fmaxf(mB[i], __shfl_xor_sync(0xffffffff, mB[i], off));
        }
    }
    if ((lane & 3) == 0) {
        int r = lane >> 2;
        unsigned int* rm = g_rowmax + nh * LQ + l0;
        #pragma unroll
        for (int i = 0; i < 2; i++) {
            atomicMax(rm + wy * 32 + i * 16 + r,     __float_as_uint(mA[i]));
            atomicMax(rm + wy * 32 + i * 16 + r + 8, __float_as_uint(mB[i]));
        }
    }
}

// ---------------------------------------------------------------------------
// Kernel D: finalize — mean (Ksum trick) + gate + masked-query output.
// ---------------------------------------------------------------------------
__global__ __launch_bounds__(256) void finalize_kernel(
    const float* __restrict__ queries,
    const float* __restrict__ qmask,
    const float* __restrict__ W,
    const float* __restrict__ bias,
    float* __restrict__ out)
{
    const int tid = threadIdx.x;
    const int g = blockIdx.x * 256 + tid;
    const int nh = g >> 11;
    const int l  = g & 2047;
    const int n  = nh >> 3;
    const int h  = nh & 7;

    __shared__ float ks_s[64];
    if (tid < 64) ks_s[tid] = g_ksum[nh * 64 + tid];
    __syncthreads();

    float mean = 0.f;
    {
        const uint4* ph = (const uint4*)(g_Qh + (size_t)g * DD);
        #pragma unroll
        for (int c = 0; c < 4; c++) {
            uint4 v = ph[c];
            const uint32_t* w32 = (const uint32_t*)&v;
            #pragma unroll
            for (int w = 0; w < 4; w++) {
                float2 f = __half22float2(*(const __half2*)&w32[w]);
                mean += f.x * ks_s[c * 16 + w * 2];
                mean += f.y * ks_s[c * 16 + w * 2 + 1];
            }
        }
    }
    mean *= (1.0f / (float)SK);
    float mx = __uint_as_float(g_rowmax[g]);
    float lg = fmaf(mean, W[0], fmaf(mx, W[1], bias[0]));
    float gate = 1.0f / (1.0f + __expf(-lg));
    float s = gate * qmask[n * LQ + l];

    size_t obase = ((((size_t)n * LQ + l) * HH + h) << 6);
    const float4* qs = (const float4*)(queries + obase);
    float4* dst = (float4*)(out + obase);
    #pragma unroll
    for (int j = 0; j < 16; j++) {
        float4 v = qs[j];
        v.x *= s; v.y *= s; v.z *= s; v.w *= s;
        dst[j] = v;
    }
}

// ---------------------------------------------------------------------------
extern "C" void kernel_launch(void* const* d_in, const int* in_sizes, int n_in,
                              void* d_out, int out_size)
{
    const float* queries = (const float*)d_in[0];
    const float* keys    = (const float*)d_in[1];
    const float* q_mask  = (const float*)d_in[3];
    const float* kv_mask = (const float*)d_in[4];
    const float* W       = (const float*)d_in[5];
    const float* b       = (const float*)d_in[6];
    float* out = (float*)d_out;

    prep_kernel<<<(NHLD / 8) / 256, 256>>>(queries, keys, q_mask, kv_mask);
    ksum_final_kernel<<<NHT, 64>>>();

    cudaFuncSetAttribute(attn_mma_kernel,
                         cudaFuncAttributeMaxDynamicSharedMemorySize, SMEM_TOTAL);
    dim3 grid(LQ / 128, NHT, ZSPLIT);
    attn_mma_kernel<<<grid, 256, SMEM_TOTAL>>>();

    finalize_kernel<<<NROWS / 256, 256>>>(queries, q_mask, W, b, out);
}

// round 10
// speedup vs baseline: 1.1624x; 1.1080x over previous
#include <cuda_runtime.h>
#include <cuda_fp16.h>
#include <math.h>
#include <stdint.h>

#define NB 2
#define LQ 2048
#define SK 2048
#define HH 8
#define DD 64
#define NHT (NB*HH)
#define NHLD (NB*HH*LQ*DD)   // 2,097,152
#define NROWS (NHT*LQ)       // 32768
#define ZSPLIT 4
#define TILES_PER_CTA 4

// Scratch (layout [n][h][row][d]), fp16
__device__ __align__(256) __half g_Qh[NHLD];
__device__ __align__(256) __half g_Kh[NHLD];
__device__ __align__(256) float g_kpart[1024*DD];   // per-prep-block partial K sums
__device__ __align__(256) unsigned int g_rowmax[NROWS];

// ---------------------------------------------------------------------------
// PTX helpers
// ---------------------------------------------------------------------------
__device__ __forceinline__ uint32_t smem_u32_of(const void* p) {
    uint32_t a;
    asm("{ .reg .u64 t; cvta.to.shared.u64 t, %1; cvt.u32.u64 %0, t; }" : "=r"(a) : "l"(p));
    return a;
}
#define LDM4(r, addr) \
    asm volatile("ldmatrix.sync.aligned.m8n8.x4.shared.b16 {%0,%1,%2,%3}, [%4];" \
        : "=r"((r)[0]), "=r"((r)[1]), "=r"((r)[2]), "=r"((r)[3]) : "r"(addr))
#define MMAF16(c, a0, a1, a2, a3, b0, b1) \
    asm volatile("mma.sync.aligned.m16n8k16.row.col.f32.f16.f16.f32 " \
        "{%0,%1,%2,%3}, {%4,%5,%6,%7}, {%8,%9}, {%0,%1,%2,%3};" \
        : "+f"((c)[0]), "+f"((c)[1]), "+f"((c)[2]), "+f"((c)[3]) \
        : "r"(a0), "r"(a1), "r"(a2), "r"(a3), "r"(b0), "r"(b1))
#define CPA16(s, g) \
    asm volatile("cp.async.cg.shared.global [%0], [%1], 16;" :: "r"(s), "l"(g))
#define CPC()  asm volatile("cp.async.commit_group;" ::: "memory")
#define CPW1() asm volatile("cp.async.wait_group 1;" ::: "memory")
#define CPW0() asm volatile("cp.async.wait_group 0;" ::: "memory")

// SMEM byte offsets (main kernel)
#define A_OFF 0
#define B_OFF 16384             // + (t%3)*16384, 3 stages
#define SMEM_TOTAL 65536

// ---------------------------------------------------------------------------
// Kernel A: feature map + mask + [n,l,h,d]->[n,h,l,d], fp16 out.
// Each block covers 32 rows of one (n,h); reduces its K rows into
// g_kpart[block][64]. Zeroes g_rowmax.
// ---------------------------------------------------------------------------
__global__ __launch_bounds__(256) void prep_kernel(
    const float* __restrict__ q, const float* __restrict__ k,
    const float* __restrict__ qm, const float* __restrict__ km)
{
    const int tid = threadIdx.x;
    int idx = blockIdx.x * 256 + tid;              // 8-element chunk index
    if (idx < NROWS) g_rowmax[idx] = 0u;

    int e = idx << 3;                              // first element
    int d = e & 63;
    int l = (e >> 6) & 2047;
    int h = (e >> 17) & 7;
    int n = e >> 20;
    size_t src = ((((size_t)n * 2048 + l) * 8 + h) << 6) + d;

    float4 q0 = *(const float4*)(q + src);
    float4 q1 = *(const float4*)(q + src + 4);
    float4 k0 = *(const float4*)(k + src);
    float4 k1 = *(const float4*)(k + src + 4);
    float qmv = qm[n * 2048 + l];
    float kmv = km[n * 2048 + l];

    float fq[8] = {q0.x, q0.y, q0.z, q0.w, q1.x, q1.y, q1.z, q1.w};
    float fk[8] = {k0.x, k0.y, k0.z, k0.w, k1.x, k1.y, k1.z, k1.w};

    float pk[8];
    uint4 oq, ok;
    uint32_t* pqo = (uint32_t*)&oq;
    uint32_t* pko = (uint32_t*)&ok;
    #pragma unroll
    for (int j = 0; j < 4; j++) {
        float ax = ((fq[2*j]   > 0.f) ? (fq[2*j]   + 1.f) : __expf(fq[2*j]))   * qmv;
        float ay = ((fq[2*j+1] > 0.f) ? (fq[2*j+1] + 1.f) : __expf(fq[2*j+1])) * qmv;
        float bx = ((fk[2*j]   > 0.f) ? (fk[2*j]   + 1.f) : __expf(fk[2*j]))   * kmv;
        float by = ((fk[2*j+1] > 0.f) ? (fk[2*j+1] + 1.f) : __expf(fk[2*j+1])) * kmv;
        pk[2*j] = bx; pk[2*j+1] = by;
        __half2 hq = __floats2half2_rn(ax, ay);
        __half2 hk = __floats2half2_rn(bx, by);
        pqo[j] = *(uint32_t*)&hq;
        pko[j] = *(uint32_t*)&hk;
    }
    ((uint4*)g_Qh)[idx] = oq;
    ((uint4*)g_Kh)[idx] = ok;

    // --- block-local K partial sum: 32 rows x 64 d -> 64 floats ---
    __shared__ float stage[32][72];
    const int row = tid >> 3;
    const int dc  = (tid & 7) * 8;
    #pragma unroll
    for (int j = 0; j < 8; j++) stage[row][dc + j] = pk[j];
    __syncthreads();
    if (tid < 64) {
        float s = 0.f;
        #pragma unroll
        for (int r = 0; r < 32; r++) s += stage[r][tid];
        g_kpart[blockIdx.x * 64 + tid] = s;
    }
}

// ---------------------------------------------------------------------------
// Kernel C: fp16 HMMA score GEMM + row-max via atomicMax (lean).
// grid=(16 ltile, 16 nh, ZSPLIT), block=256 (8 warps 4x2), 2 CTAs/SM.
// ---------------------------------------------------------------------------
__global__ void __launch_bounds__(256, 2) attn_mma_kernel()
{
    extern __shared__ char sm[];
    const uint32_t smu = smem_u32_of(sm);

    const int tid  = threadIdx.x;
    const int lane = tid & 31;
    const int wid  = tid >> 5;
    const int wx   = wid & 1;       // n-block (64 cols)
    const int wy   = wid >> 1;      // m-block (32 rows)
    const int nh   = blockIdx.y;
    const int l0   = blockIdx.x * 128;
    const int ts0  = blockIdx.z * TILES_PER_CTA;

    const int mat    = lane >> 3;
    const int rin    = lane & 7;
    const int a_row  = wy * 32 + (mat & 1) * 8 + rin;
    const int a_kc   = mat >> 1;
    const int b_roff = wx * 64 + (mat >> 1) * 8 + rin;
    const int b_kc   = mat & 1;

    const char* kh_base = (const char*)(g_Kh + (size_t)nh * SK * DD);

    auto issue_b = [&](int t) {
        uint32_t bu = smu + B_OFF + (t % 3) * 16384;
        const char* gk = kh_base + (size_t)(ts0 + t) * 128 * DD * 2;
        #pragma unroll
        for (int kk = 0; kk < 4; kk++) {
            int c = tid + kk * 256;
            int row = c >> 3, dc = c & 7;
            uint32_t sw = row * 128 + ((dc ^ (row & 7)) << 4);
            CPA16(bu + sw, gk + c * 16);
        }
    };

    issue_b(0); CPC();
    issue_b(1); CPC();

    // --- A tile (Q fp16, 128 x 64): LDG + swizzled STS (overlaps cp.async) ---
    {
        const char* qh = (const char*)(g_Qh + ((size_t)nh * LQ + l0) * DD);
        #pragma unroll
        for (int c = tid; c < 1024; c += 256) {
            int row = c >> 3, dc = c & 7;
            uint32_t dst = row * 128 + ((dc ^ (row & 7)) << 4);
            *(uint4*)(sm + A_OFF + dst) = *(const uint4*)(qh + c * 16);
        }
    }

    float mA[2] = {0.f, 0.f};
    float mB[2] = {0.f, 0.f};

    for (int t = 0; t < TILES_PER_CTA; t++) {
        if (t + 1 < TILES_PER_CTA) { CPW1(); }
        else                       { CPW0(); }
        __syncthreads();                        // stage t visible; t-1 compute done
        if (t + 2 < TILES_PER_CTA) { issue_b(t + 2); CPC(); }

        const uint32_t Bu = smu + B_OFF + (t % 3) * 16384;
        float acc[2][8][4];
        #pragma unroll
        for (int i = 0; i < 2; i++)
            #pragma unroll
            for (int j = 0; j < 8; j++)
                acc[i][j][0] = acc[i][j][1] = acc[i][j][2] = acc[i][j][3] = 0.f;

        #pragma unroll
        for (int ks = 0; ks < 4; ks++) {
            const int kb = ks * 2;
            uint32_t ah[2][4];
            #pragma unroll
            for (int i = 0; i < 2; i++) {
                int ar = a_row + 16 * i;
                uint32_t ad = smu + A_OFF + ar * 128 + (((a_kc + kb) ^ (ar & 7)) << 4);
                LDM4(ah[i], ad);
            }
            uint32_t rb[4][4];
            #pragma unroll
            for (int jp = 0; jp < 4; jp++) {
                int br = b_roff + jp * 16;
                uint32_t bd = Bu + br * 128 + (((b_kc + kb) ^ (br & 7)) << 4);
                LDM4(rb[jp], bd);
            }
            #pragma unroll
            for (int jp = 0; jp < 4; jp++)
                #pragma unroll
                for (int i = 0; i < 2; i++) {
                    MMAF16(acc[i][jp*2],   ah[i][0], ah[i][1], ah[i][2], ah[i][3], rb[jp][0], rb[jp][1]);
                    MMAF16(acc[i][jp*2+1], ah[i][0], ah[i][1], ah[i][2], ah[i][3], rb[jp][2], rb[jp][3]);
                }
        }

        #pragma unroll
        for (int i = 0; i < 2; i++)
            #pragma unroll
            for (int j = 0; j < 8; j++) {
                mA[i] = fmaxf(mA[i], fmaxf(acc[i][j][0], acc[i][j][1]));
                mB[i] = fmaxf(mB[i], fmaxf(acc[i][j][2], acc[i][j][3]));
            }
    }

    // --- reduce max across lane%4, atomicMax (uint order == float order, >=0) ---
    #pragma unroll
    for (int off = 1; off <= 2; off <<= 1) {
        #pragma unroll
        for (int i = 0; i < 2; i++) {
            mA[i] = fmaxf(mA[i], __shfl_xor_sync(0xffffffff, mA[i], off));
            mB[i] = fmaxf(mB[i], __shfl_xor_sync(0xffffffff, mB[i], off));
        }
    }
    if ((lane & 3) == 0) {
        int r = lane >> 2;
        unsigned int* rm = g_rowmax + nh * LQ + l0;
        #pragma unroll
        for (int i = 0; i < 2; i++) {
            atomicMax(rm + wy * 32 + i * 16 + r,     __float_as_uint(mA[i]));
            atomicMax(rm + wy * 32 + i * 16 + r + 8, __float_as_uint(mB[i]));
        }
    }
}

// ---------------------------------------------------------------------------
// Kernel D: finalize — ksum reduce + mean + gate + output.
// grid = 512 blocks; each block = 64 rows of one nh, 4 threads per row.
// ---------------------------------------------------------------------------
__global__ __launch_bounds__(256) void finalize_kernel(
    const float* __restrict__ queries,
    const float* __restrict__ qmask,
    const float* __restrict__ W,
    const float* __restrict__ bias,
    float* __restrict__ out)
{
    const int tid  = threadIdx.x;
    const int lane = tid & 31;
    const int r0   = blockIdx.x * 64;         // first global row of this block
    const int nh   = r0 >> 11;
    const int n    = nh >> 3;
    const int h    = nh & 7;

    // --- ksum[nh][64] from per-prep-block partials (64 blocks per nh, L2-hot) ---
    __shared__ float ks_s[64];
    if (tid < 64) {
        const float* kp = g_kpart + (nh << 12) + tid;   // nh*64*64 + d
        float s = 0.f;
        #pragma unroll 16
        for (int b = 0; b < 64; b++) s += kp[b * 64];
        ks_s[tid] = s;
    }
    __syncthreads();

    // --- 4 threads per row ---
    const int rrow = tid >> 2;                // 0..63 row within block
    const int sub  = tid & 3;                 // quad lane
    const int grow = r0 + rrow;               // global row (nh*2048 + l)
    const int l    = grow & 2047;

    // partial mean: 16 d's per thread = 2x uint4 of fp16
    float mean = 0.f;
    {
        const uint4* ph = (const uint4*)(g_Qh + (size_t)grow * DD) + sub * 2;
        #pragma unroll
        for (int c = 0; c < 2; c++) {
            uint4 v = ph[c];
            const uint32_t* w32 = (const uint32_t*)&v;
            const int db = sub * 16 + c * 8;
            #pragma unroll
            for (int w = 0; w < 4; w++) {
                float2 f = __half22float2(*(const __half2*)&w32[w]);
                mean += f.x * ks_s[db + w * 2];
                mean += f.y * ks_s[db + w * 2 + 1];
            }
        }
    }
    // reduce across the quad (lanes sub=0..3 of same row)
    mean += __shfl_xor_sync(0xffffffff, mean, 1);
    mean += __shfl_xor_sync(0xffffffff, mean, 2);
    mean *= (1.0f / (float)SK);

    float mx = __uint_as_float(g_rowmax[grow]);
    float lg = fmaf(mean, W[0], fmaf(mx, W[1], bias[0]));
    float gate = 1.0f / (1.0f + __expf(-lg));
    float s = gate * qmask[n * LQ + l];

    // each quad-lane writes 16 floats (64B) of the 64-float row
    size_t obase = ((((size_t)n * LQ + l) * HH + h) << 6) + sub * 16;
    const float4* qs = (const float4*)(queries + obase);
    float4* dst = (float4*)(out + obase);
    #pragma unroll
    for (int j = 0; j < 4; j++) {
        float4 v = qs[j];
        v.x *= s; v.y *= s; v.z *= s; v.w *= s;
        dst[j] = v;
    }
}

// ---------------------------------------------------------------------------
extern "C" void kernel_launch(void* const* d_in, const int* in_sizes, int n_in,
                              void* d_out, int out_size)
{
    const float* queries = (const float*)d_in[0];
    const float* keys    = (const float*)d_in[1];
    const float* q_mask  = (const float*)d_in[3];
    const float* kv_mask = (const float*)d_in[4];
    const float* W       = (const float*)d_in[5];
    const float* b       = (const float*)d_in[6];
    float* out = (float*)d_out;

    prep_kernel<<<(NHLD / 8) / 256, 256>>>(queries, keys, q_mask, kv_mask);

    cudaFuncSetAttribute(attn_mma_kernel,
                         cudaFuncAttributeMaxDynamicSharedMemorySize, SMEM_TOTAL);
    dim3 grid(LQ / 128, NHT, ZSPLIT);
    attn_mma_kernel<<<grid, 256, SMEM_TOTAL>>>();

    finalize_kernel<<<NROWS / 64, 256>>>(queries, q_mask, W, b, out);
}